// round 1
// baseline (speedup 1.0000x reference)
#include <cuda_runtime.h>
#include <math.h>

// Problem constants
#define DIMD 300
#define NB   16
#define TA   2000
#define NQ   30
#define NOPT 16
// ContractExpand ranges: r={1,2,4,10,25}, groups g={2000,1000,500,200,80}
// Row-block layout for xs/h: ranges concatenated, each range contiguous [B, g_i, D]
// Row offsets (in rows): {0, 32000, 48000, 56000, 59200}, total 60480

// ---------------- scratch (device globals; no allocation allowed) ----------------
__device__ float g_art[32000 * 300];
__device__ float g_q[480 * 300];
__device__ float g_opt[1024 * 300];      // [opt][b][w][d]
__device__ float g_xs[60480 * 300];
__device__ float g_h[60480 * 300];
__device__ float g_gate[32000 * 300];
__device__ float g_z[32000 * 300];
__device__ float g_o[32000 * 300];
__device__ float g_enc[32000 * 300];
__device__ float g_aoq[32000 * 300];
__device__ float g_k1[480 * 300];
__device__ float g_k2[1024 * 300];
__device__ float g_k3[1024 * 300];
__device__ float g_sA[16 * 40 * 300];
__device__ float g_sB[16 * 40 * 300];
__device__ float g_sC[16 * 40 * 300];
__device__ float g_cm[4 * 16 * 2 * 16];  // [opt][b][{aoqo,ooa}][w] column sums of probs

// buffer selector (avoids host-side symbol address lookups)
__device__ __forceinline__ float* bufsel(int s) {
    switch (s) {
        case 0: return g_art;
        case 1: return g_q;
        case 2: return g_opt;
        case 3: return g_xs;
        case 4: return g_h;
        case 5: return g_z;
        case 6: return g_o;
        case 8: return g_aoq;
        case 9: return g_k1;
        case 10: return g_k2;
        default: return g_k3;  // 11
    }
}

// ---------------- embedding gather ----------------
__global__ void gather_kernel(const int* __restrict__ idx, const float* __restrict__ emb,
                              int dsel, int rowOff, int nrows) {
    int i = blockIdx.x * blockDim.x + threadIdx.x;
    int total = nrows * 300;
    if (i >= total) return;
    int r = i / 300;
    int d = i - r * 300;
    float* out = bufsel(dsel) + rowOff * 300;
    out[i] = emb[idx[r] * 300 + d];
}

// ---------------- group sums (xs) ----------------
__global__ void xs_kernel() {
    int i = blockIdx.x * blockDim.x + threadIdx.x;
    if (i >= 60480 * 300) return;
    int R = i / 300;
    int d = i - R * 300;
    float s = 0.f;
    if (R < 32000) {  // r=1, direct copy
        g_xs[i] = g_art[i];
        return;
    } else if (R < 48000) {  // r=2
        int L = R - 32000; int b = L / 1000; int g = L - b * 1000;
        int base = (b * 2000 + g * 2) * 300 + d;
        s = g_art[base] + g_art[base + 300];
    } else if (R < 56000) {  // r=4
        int L = R - 48000; int b = L / 500; int g = L - b * 500;
        int base = (b * 2000 + g * 4) * 300 + d;
        #pragma unroll
        for (int j = 0; j < 4; j++) s += g_art[base + j * 300];
    } else if (R < 59200) {  // r=10
        int L = R - 56000; int b = L / 200; int g = L - b * 200;
        int base = (b * 2000 + g * 10) * 300 + d;
        #pragma unroll
        for (int j = 0; j < 10; j++) s += g_art[base + j * 300];
    } else {  // r=25
        int L = R - 59200; int b = L / 80; int g = L - b * 80;
        int base = (b * 2000 + g * 25) * 300 + d;
        #pragma unroll
        for (int j = 0; j < 25; j++) s += g_art[base + j * 300];
    }
    g_xs[i] = s;
}

// ---------------- generic tiled SGEMM: C = act(A(M,K) @ B(N,K)^T + bias) ----------------
// act: 0=none, 1=relu, 2=tanh. ceMode: select per-range ce weights from block row.
__global__ void gemm_kernel(int Asel, const float* __restrict__ Bw,
                            const float* __restrict__ bias, int Csel,
                            int M, int N, int K, int act, int ceMode) {
    __shared__ float As[8][65];
    __shared__ float Bs[8][65];
    const float* A = bufsel(Asel);
    float* C = bufsel(Csel);
    int bm = blockIdx.y * 64, bn = blockIdx.x * 64;
    if (ceMode) {
        int ri;
        if (bm < 32000) ri = 0;
        else if (bm < 48000) ri = 1;
        else if (bm < 56000) ri = 2;
        else if (bm < 59200) ri = 3;
        else ri = 4;
        Bw += ri * 90000;
        bias += ri * 300;
    }
    int tid = threadIdx.x;
    int ty = tid >> 4, tx = tid & 15;
    float acc[4][4];
    #pragma unroll
    for (int i = 0; i < 4; i++)
        #pragma unroll
        for (int j = 0; j < 4; j++) acc[i][j] = 0.f;

    for (int kt = 0; kt < K; kt += 8) {
        #pragma unroll
        for (int l = 0; l < 2; l++) {
            int idx = tid + l * 256;
            int m0 = idx >> 3, k0 = idx & 7;
            int gm = bm + m0, gk = kt + k0;
            As[k0][m0] = (gm < M && gk < K) ? A[gm * K + gk] : 0.f;
            int gn = bn + m0;
            Bs[k0][m0] = (gn < N && gk < K) ? Bw[gn * K + gk] : 0.f;
        }
        __syncthreads();
        #pragma unroll
        for (int k = 0; k < 8; k++) {
            float a[4], b[4];
            #pragma unroll
            for (int i = 0; i < 4; i++) a[i] = As[k][ty * 4 + i];
            #pragma unroll
            for (int j = 0; j < 4; j++) b[j] = Bs[k][tx * 4 + j];
            #pragma unroll
            for (int i = 0; i < 4; i++)
                #pragma unroll
                for (int j = 0; j < 4; j++) acc[i][j] += a[i] * b[j];
        }
        __syncthreads();
    }
    #pragma unroll
    for (int i = 0; i < 4; i++) {
        int m = bm + ty * 4 + i;
        if (m >= M) continue;
        #pragma unroll
        for (int j = 0; j < 4; j++) {
            int n = bn + tx * 4 + j;
            if (n >= N) continue;
            float v = acc[i][j] + bias[n];
            if (act == 1) v = fmaxf(v, 0.f);
            else if (act == 2) v = tanhf(v);
            C[m * N + n] = v;
        }
    }
}

// ---------------- gate: tiny 5->3->1 MLP over stacked range features ----------------
__global__ void gate_kernel(const float* __restrict__ mr1W, const float* __restrict__ mr1b,
                            const float* __restrict__ mr2W, const float* __restrict__ mr2b) {
    int i = blockIdx.x * blockDim.x + threadIdx.x;
    if (i >= 32000 * 300) return;
    int bt = i / 300;
    int d = i - bt * 300;
    int b = bt / 2000;
    int t = bt - b * 2000;
    float y[5];
    y[0] = g_h[(b * 2000 + t) * 300 + d];
    y[1] = g_h[(32000 + b * 1000 + (t >> 1)) * 300 + d] * 0.5f;
    y[2] = g_h[(48000 + b * 500 + (t >> 2)) * 300 + d] * 0.25f;
    y[3] = g_h[(56000 + b * 200 + t / 10) * 300 + d] * (1.0f / 10.0f);
    y[4] = g_h[(59200 + b * 80 + t / 25) * 300 + d] * (1.0f / 25.0f);
    float acc2 = __ldg(mr2b);
    #pragma unroll
    for (int k = 0; k < 3; k++) {
        float hk = __ldg(&mr1b[k]);
        #pragma unroll
        for (int r = 0; r < 5; r++) hk += __ldg(&mr1W[k * 5 + r]) * y[r];
        hk = fmaxf(hk, 0.f);
        acc2 += __ldg(&mr2W[k]) * hk;
    }
    g_gate[i] = fmaxf(acc2, 0.f);
}

// ---------------- chunked linear scan: c_t = g*c + (1-g)*z ----------------
// 40 chunks of 50 steps. Pass A: per-chunk affine (a,b). Pass B: chunk prefix. Pass C: final + h=o*c.
__global__ void scanA_kernel() {
    int ch = blockIdx.x, b = blockIdx.y, d = threadIdx.x;
    int base = (b * 2000 + ch * 50) * 300 + d;
    float a = 1.f, bb = 0.f;
    for (int j = 0; j < 50; j++) {
        float g = g_gate[base + j * 300];
        float z = g_z[base + j * 300];
        a *= g;
        bb = g * (bb - z) + z;
    }
    int o = (b * 40 + ch) * 300 + d;
    g_sA[o] = a;
    g_sB[o] = bb;
}
__global__ void scanB_kernel() {
    int b = blockIdx.x, d = threadIdx.x;
    float c = 0.f;
    for (int ch = 0; ch < 40; ch++) {
        int o = (b * 40 + ch) * 300 + d;
        g_sC[o] = c;
        c = g_sA[o] * c + g_sB[o];
    }
}
__global__ void scanC_kernel() {
    int ch = blockIdx.x, b = blockIdx.y, d = threadIdx.x;
    float c = g_sC[(b * 40 + ch) * 300 + d];
    int base = (b * 2000 + ch * 50) * 300 + d;
    for (int j = 0; j < 50; j++) {
        float g = g_gate[base + j * 300];
        float z = g_z[base + j * 300];
        c = g * (c - z) + z;
        g_enc[base + j * 300] = g_o[base + j * 300] * c;
    }
}

// ---------------- attention 1: aoq = softmax(enc . k1) @ q ----------------
__global__ void attn1_kernel() {
    __shared__ float sk[30][301];
    __shared__ float srow[8][300];
    __shared__ float sp[8][30];
    int b = blockIdx.y;
    int tid = threadIdx.x;
    for (int i = tid; i < 30 * 300; i += 256) {
        int w = i / 300, k = i - w * 300;
        sk[w][k] = g_k1[(b * 30 + w) * 300 + k];
    }
    __syncthreads();
    int warp = tid >> 5, lane = tid & 31;
    int t = blockIdx.x * 8 + warp;
    const float* row = g_enc + (b * 2000 + t) * 300;
    for (int dd = lane; dd < 300; dd += 32) srow[warp][dd] = row[dd];
    __syncwarp();
    float s = -1e30f;
    if (lane < 30) {
        float a = 0.f;
        for (int k = 0; k < 300; k++) a += srow[warp][k] * sk[lane][k];
        s = a;
    }
    float mx = s;
    #pragma unroll
    for (int o = 16; o; o >>= 1) mx = fmaxf(mx, __shfl_xor_sync(0xffffffffu, mx, o));
    float e = (lane < 30) ? expf(s - mx) : 0.f;
    float sum = e;
    #pragma unroll
    for (int o = 16; o; o >>= 1) sum += __shfl_xor_sync(0xffffffffu, sum, o);
    if (lane < 30) sp[warp][lane] = e / sum;
    __syncwarp();
    const float* qb = g_q + b * 30 * 300;
    float* outr = g_aoq + (b * 2000 + t) * 300;
    for (int dd = lane; dd < 300; dd += 32) {
        float a = 0.f;
        #pragma unroll 5
        for (int w = 0; w < 30; w++) a += sp[warp][w] * qb[w * 300 + dd];
        outr[dd] = a;
    }
}

// ---------------- attention 2: column-sums of softmax(aoq . k2) and softmax(aoq . k3) ----------------
// Lanes 0-15 handle keys2 (aoqo), lanes 16-31 handle keys3 (ooa). Softmax within 16-lane halves.
__global__ void attn2_kernel() {
    __shared__ float sk2[16][301];
    __shared__ float sk3[16][301];
    __shared__ float srow[8][300];
    int ch = blockIdx.x, b = blockIdx.y, opt = blockIdx.z;
    int tid = threadIdx.x, warp = tid >> 5, lane = tid & 31;
    int ob = opt * 16 + b;
    for (int i = tid; i < 16 * 300; i += 256) {
        int w = i / 300, k = i - w * 300;
        sk2[w][k] = g_k2[(ob * 16 + w) * 300 + k];
        sk3[w][k] = g_k3[(ob * 16 + w) * 300 + k];
    }
    __syncthreads();
    const float* kp = (lane < 16) ? &sk2[lane][0] : &sk3[lane - 16][0];
    float acc = 0.f;
    for (int t = ch * 250 + warp; t < ch * 250 + 250; t += 8) {
        const float* row = g_aoq + (b * 2000 + t) * 300;
        for (int dd = lane; dd < 300; dd += 32) srow[warp][dd] = row[dd];
        __syncwarp();
        float s = 0.f;
        for (int k = 0; k < 300; k++) s += srow[warp][k] * kp[k];
        float mx = s;
        #pragma unroll
        for (int o = 8; o; o >>= 1) mx = fmaxf(mx, __shfl_xor_sync(0xffffffffu, mx, o));
        float e = expf(s - mx);
        float sum = e;
        #pragma unroll
        for (int o = 8; o; o >>= 1) sum += __shfl_xor_sync(0xffffffffu, sum, o);
        acc += e / sum;
        __syncwarp();
    }
    atomicAdd(&g_cm[(ob * 2 + (lane >> 4)) * 16 + (lane & 15)], acc);
}

__global__ void zero_cm_kernel() {
    int i = blockIdx.x * blockDim.x + threadIdx.x;
    if (i < 4 * 16 * 2 * 16) g_cm[i] = 0.f;
}

// ---------------- final: answer vectors + 600->75->1 MLP ----------------
__global__ void final_kernel(const float* __restrict__ as1W, const float* __restrict__ as1b,
                             const float* __restrict__ as2W, const float* __restrict__ as2b,
                             float* __restrict__ out) {
    __shared__ float sav[600];
    __shared__ float sh[75];
    __shared__ float scm[32];
    int bid = blockIdx.x;
    int opt = bid >> 4, b = bid & 15;
    int ob = opt * 16 + b;
    int tid = threadIdx.x;
    if (tid < 32) scm[tid] = g_cm[ob * 32 + tid] * (1.0f / 2000.0f);
    __syncthreads();
    for (int d = tid; d < 300; d += 128) {
        float a2 = 0.f, a3 = 0.f;
        #pragma unroll
        for (int w = 0; w < 16; w++) {
            float ov = g_opt[(ob * 16 + w) * 300 + d];
            a2 += scm[w] * ov;
            a3 += scm[16 + w] * ov;
        }
        sav[d] = a2;
        sav[300 + d] = a3;
    }
    __syncthreads();
    for (int j = tid; j < 75; j += 128) {
        float a = __ldg(&as1b[j]);
        for (int i2 = 0; i2 < 600; i2++) a += __ldg(&as1W[j * 600 + i2]) * sav[i2];
        sh[j] = fmaxf(a, 0.f);
    }
    __syncthreads();
    if (tid == 0) {
        float s = __ldg(as2b);
        for (int j = 0; j < 75; j++) s += __ldg(&as2W[j]) * sh[j];
        out[b * 4 + opt] = s;
    }
}

// ---------------- launch ----------------
extern "C" void kernel_launch(void* const* d_in, const int* in_sizes, int n_in,
                              void* d_out, int out_size) {
    const int* opt_idx[4] = {(const int*)d_in[0], (const int*)d_in[1],
                             (const int*)d_in[2], (const int*)d_in[3]};
    const int* q_idx = (const int*)d_in[4];
    const int* a_idx = (const int*)d_in[5];
    const float* emb = (const float*)d_in[6];
    const float* ceW = (const float*)d_in[7];
    const float* ceb = (const float*)d_in[8];
    const float* mr1W = (const float*)d_in[9];
    const float* mr1b = (const float*)d_in[10];
    const float* mr2W = (const float*)d_in[11];
    const float* mr2b = (const float*)d_in[12];
    const float* Wz = (const float*)d_in[13];
    const float* bz = (const float*)d_in[14];
    const float* Wo = (const float*)d_in[15];
    const float* bo = (const float*)d_in[16];
    const float* f1W = (const float*)d_in[17];
    const float* f1b = (const float*)d_in[18];
    const float* f2W = (const float*)d_in[19];
    const float* f2b = (const float*)d_in[20];
    const float* f3W = (const float*)d_in[21];
    const float* f3b = (const float*)d_in[22];
    const float* as1W = (const float*)d_in[23];
    const float* as1b = (const float*)d_in[24];
    const float* as2W = (const float*)d_in[25];
    const float* as2b = (const float*)d_in[26];

    // embeddings
    gather_kernel<<<(32000 * 300 + 255) / 256, 256>>>(a_idx, emb, 0, 0, 32000);
    gather_kernel<<<(480 * 300 + 255) / 256, 256>>>(q_idx, emb, 1, 0, 480);
    for (int o = 0; o < 4; o++)
        gather_kernel<<<(256 * 300 + 255) / 256, 256>>>(opt_idx[o], emb, 2, o * 256, 256);

    // ContractExpand: group sums, then batched per-range GEMM (relu)
    xs_kernel<<<(60480 * 300 + 255) / 256, 256>>>();
    {
        dim3 g((300 + 63) / 64, (60480 + 63) / 64);
        gemm_kernel<<<g, 256>>>(3, ceW, ceb, 4, 60480, 300, 300, 1, 1);
    }
    gate_kernel<<<(32000 * 300 + 255) / 256, 256>>>(mr1W, mr1b, mr2W, mr2b);

    // z, o projections (tanh)
    {
        dim3 g((300 + 63) / 64, (32000 + 63) / 64);
        gemm_kernel<<<g, 256>>>(0, Wz, bz, 5, 32000, 300, 300, 2, 0);
        gemm_kernel<<<g, 256>>>(0, Wo, bo, 6, 32000, 300, 300, 2, 0);
    }

    // chunked scan -> enc
    scanA_kernel<<<dim3(40, 16), 300>>>();
    scanB_kernel<<<16, 300>>>();
    scanC_kernel<<<dim3(40, 16), 300>>>();

    // attention 1
    {
        dim3 g((300 + 63) / 64, (480 + 63) / 64);
        gemm_kernel<<<g, 256>>>(1, f1W, f1b, 9, 480, 300, 300, 0, 0);
    }
    attn1_kernel<<<dim3(250, 16), 256>>>();

    // option keys + attention 2 column sums
    {
        dim3 g((300 + 63) / 64, (1024 + 63) / 64);
        gemm_kernel<<<g, 256>>>(2, f2W, f2b, 10, 1024, 300, 300, 0, 0);
        gemm_kernel<<<g, 256>>>(2, f3W, f3b, 11, 1024, 300, 300, 0, 0);
    }
    zero_cm_kernel<<<8, 256>>>();
    attn2_kernel<<<dim3(8, 16, 4), 256>>>();

    // final MLP
    final_kernel<<<64, 128>>>(as1W, as1b, as2W, as2b, (float*)d_out);
}

// round 3
// speedup vs baseline: 1.6153x; 1.6153x over previous
#include <cuda_runtime.h>
#include <cuda_bf16.h>
#include <math.h>

// Constants: DIM=300, B=16, T=2000, Tq=30, Topt=16, K padded to 304 (19 k16 stages)
#define KP 304
#define NSTAGE 19
// CE padded row layout (128-aligned range starts): 0,32000,48000,56064,59392; M=60672

typedef __nv_bfloat16 bf16;

// ---------------- scratch ----------------
__device__ float g_art[32000 * 300];
__device__ bf16  g_arth[32000 * KP], g_artl[32000 * KP];
__device__ bf16  g_xsh[60672 * KP],  g_xsl[60672 * KP];
__device__ float g_h[60672 * 300];
__device__ float g_gate[32000 * 300];
__device__ float g_z[32000 * 300];
__device__ float g_o[32000 * 300];
__device__ float g_enc[32000 * 300];
__device__ float g_aoq[32000 * 300];
__device__ float g_qf[480 * 300];
__device__ bf16  g_qh[512 * KP], g_ql[512 * KP];
__device__ float g_optf[1024 * 300];
__device__ bf16  g_opth[1024 * KP], g_optl[1024 * KP];
__device__ float g_k1[480 * 300], g_k2[1024 * 300], g_k3[1024 * 300];
__device__ float g_scA[16 * 40 * 300], g_scB[16 * 40 * 300], g_scC[16 * 40 * 300];
__device__ float g_cm[4 * 16 * 2 * 16];
// weights: 10 slots of [320][KP] bf16 (0-4 ce, 5 Wz, 6 Wo, 7 f1, 8 f2, 9 f3)
#define WSLOT (320 * KP)
__device__ bf16 g_wh[10 * WSLOT], g_wl[10 * WSLOT];

// ---------------- helpers ----------------
__device__ __forceinline__ void split2(float x, bf16& h, bf16& l) {
    h = __float2bfloat16(x);
    l = __float2bfloat16(x - __bfloat162float(h));
}

__device__ __forceinline__ void cp16(void* s, const void* g) {
    unsigned sa = (unsigned)__cvta_generic_to_shared(s);
    asm volatile("cp.async.cg.shared.global [%0], [%1], 16;" :: "r"(sa), "l"(g));
}

__device__ __forceinline__ void mma16816(float* c, const unsigned* a, const unsigned* b) {
    asm volatile(
        "mma.sync.aligned.m16n8k16.row.col.f32.bf16.bf16.f32 "
        "{%0,%1,%2,%3}, {%4,%5,%6,%7}, {%8,%9}, {%0,%1,%2,%3};\n"
        : "+f"(c[0]), "+f"(c[1]), "+f"(c[2]), "+f"(c[3])
        : "r"(a[0]), "r"(a[1]), "r"(a[2]), "r"(a[3]), "r"(b[0]), "r"(b[1]));
}

// ---------------- weight prep: fp32 -> bf16 hi/lo, padded [320][KP] ----------------
__global__ void split_w(const float* __restrict__ src, int slotBase, int count) {
    int i = blockIdx.x * blockDim.x + threadIdx.x;
    if (i >= count) return;
    int slot = slotBase + i / 90000;
    int rem = i % 90000;
    int n = rem / 300, k = rem - n * 300;
    bf16 h, l; split2(src[i], h, l);
    int o = slot * WSLOT + n * KP + k;
    g_wh[o] = h; g_wl[o] = l;
}

// ---------------- embedding gather + split ----------------
__global__ void gather_split(const int* __restrict__ idx, const float* __restrict__ emb,
                             int sel, int rowOff, int nrows) {
    int i = blockIdx.x * blockDim.x + threadIdx.x;
    if (i >= nrows * 300) return;
    int r = i / 300, d = i - r * 300;
    float x = emb[idx[r] * 300 + d];
    int R = rowOff + r;
    float* f; bf16 *h, *l;
    if (sel == 0) { f = g_art; h = g_arth; l = g_artl; }
    else if (sel == 1) { f = g_qf; h = g_qh; l = g_ql; }
    else { f = g_optf; h = g_opth; l = g_optl; }
    f[R * 300 + d] = x;
    bf16 hb, lb; split2(x, hb, lb);
    h[R * KP + d] = hb;
    l[R * KP + d] = lb;
}

// ---------------- group sums (xs) -> split bf16, padded layout ----------------
__global__ void xs_kernel() {
    int i = blockIdx.x * blockDim.x + threadIdx.x;
    if (i >= 60672 * 300) return;
    int R = i / 300, d = i - R * 300;
    float s;
    if (R < 32000) {
        s = g_art[R * 300 + d];
    } else if (R < 48000) {
        int L = R - 32000, b = L / 1000, g = L - b * 1000;
        int base = (b * 2000 + g * 2) * 300 + d;
        s = g_art[base] + g_art[base + 300];
    } else if (R < 56000) {
        int L = R - 48000, b = L / 500, g = L - b * 500;
        int base = (b * 2000 + g * 4) * 300 + d;
        s = 0.f;
        #pragma unroll
        for (int j = 0; j < 4; j++) s += g_art[base + j * 300];
    } else if (R < 56064) {
        return;  // pad rows stay zero
    } else if (R < 59264) {
        int L = R - 56064, b = L / 200, g = L - b * 200;
        int base = (b * 2000 + g * 10) * 300 + d;
        s = 0.f;
        #pragma unroll
        for (int j = 0; j < 10; j++) s += g_art[base + j * 300];
    } else if (R < 59392) {
        return;  // pad
    } else {
        int L = R - 59392, b = L / 80, g = L - b * 80;
        int base = (b * 2000 + g * 25) * 300 + d;
        s = 0.f;
        #pragma unroll
        for (int j = 0; j < 25; j++) s += g_art[base + j * 300];
    }
    bf16 h, l; split2(s, h, l);
    g_xsh[R * KP + d] = h;
    g_xsl[R * KP + d] = l;
}

// ---------------- tensor-core GEMM: C = act(A(M,300) @ W(300,300)^T + bias) ----------------
// bf16 2-split (hh + hl + lh) for fp32-grade accuracy. Tile 128Mx64N, 2-stage cp.async.
#define SAST 24   // smem row stride (bf16) -> conflict-free frag loads
__global__ void __launch_bounds__(256) gemm_mma(int Asel, int wslot, const float* __restrict__ bias,
                                                int Csel, int M, int act, int ceMode) {
    __shared__ __align__(16) bf16 sA[2][2][128 * SAST];
    __shared__ __align__(16) bf16 sB[2][2][64 * SAST];

    const bf16 *Ah, *Al;
    switch (Asel) {
        case 0: Ah = g_xsh;  Al = g_xsl;  break;
        case 1: Ah = g_arth; Al = g_artl; break;
        case 2: Ah = g_qh;   Al = g_ql;   break;
        default: Ah = g_opth; Al = g_optl; break;
    }
    float* C;
    switch (Csel) {
        case 0: C = g_h; break;
        case 1: C = g_z; break;
        case 2: C = g_o; break;
        case 3: C = g_k1; break;
        case 4: C = g_k2; break;
        default: C = g_k3; break;
    }
    int bm = blockIdx.y * 128, bn = blockIdx.x * 64;
    int slot = wslot;
    if (ceMode) {
        slot = (bm < 32000) ? 0 : (bm < 48000) ? 1 : (bm < 56064) ? 2 : (bm < 59392) ? 3 : 4;
        bias += slot * 300;
    }
    const bf16* Wh = g_wh + slot * WSLOT;
    const bf16* Wl = g_wl + slot * WSLOT;

    int tid = threadIdx.x;
    int lane = tid & 31, warp = tid >> 5;
    int wm = warp & 3, wn = warp >> 2;

    // issue one stage of cp.async
    auto issue = [&](int s, int buf) {
        int kt = s * 16;
        int row = tid >> 1, kh = (tid & 1) * 8;
        cp16(&sA[buf][0][row * SAST + kh], Ah + (size_t)(bm + row) * KP + kt + kh);
        cp16(&sA[buf][1][row * SAST + kh], Al + (size_t)(bm + row) * KP + kt + kh);
        if (tid < 128) {
            int br = tid >> 1, bkh = (tid & 1) * 8;
            cp16(&sB[buf][0][br * SAST + bkh], Wh + (size_t)(bn + br) * KP + kt + bkh);
        } else {
            int t = tid - 128;
            int br = t >> 1, bkh = (t & 1) * 8;
            cp16(&sB[buf][1][br * SAST + bkh], Wl + (size_t)(bn + br) * KP + kt + bkh);
        }
        asm volatile("cp.async.commit_group;");
    };

    float acc[2][4][4];
    #pragma unroll
    for (int mi = 0; mi < 2; mi++)
        #pragma unroll
        for (int ni = 0; ni < 4; ni++)
            #pragma unroll
            for (int j = 0; j < 4; j++) acc[mi][ni][j] = 0.f;

    issue(0, 0);
    issue(1, 1);
    asm volatile("cp.async.wait_group 1;");
    __syncthreads();

    int r0 = wm * 32 + (lane >> 2);
    int kc = lane & 3;
    int nb0 = wn * 32 + (lane >> 2);

    for (int s = 0; s < NSTAGE; s++) {
        int buf = s & 1;
        const unsigned* A32h = (const unsigned*)sA[buf][0];
        const unsigned* A32l = (const unsigned*)sA[buf][1];
        const unsigned* B32h = (const unsigned*)sB[buf][0];
        const unsigned* B32l = (const unsigned*)sB[buf][1];
        unsigned ah[2][4], al[2][4], bh[4][2], bl[4][2];
        #pragma unroll
        for (int mi = 0; mi < 2; mi++) {
            int r = r0 + mi * 16;
            int i0 = r * (SAST / 2) + kc;
            int i1 = (r + 8) * (SAST / 2) + kc;
            ah[mi][0] = A32h[i0];     ah[mi][1] = A32h[i1];
            ah[mi][2] = A32h[i0 + 4]; ah[mi][3] = A32h[i1 + 4];
            al[mi][0] = A32l[i0];     al[mi][1] = A32l[i1];
            al[mi][2] = A32l[i0 + 4]; al[mi][3] = A32l[i1 + 4];
        }
        #pragma unroll
        for (int ni = 0; ni < 4; ni++) {
            int n = nb0 + ni * 8;
            int i0 = n * (SAST / 2) + kc;
            bh[ni][0] = B32h[i0]; bh[ni][1] = B32h[i0 + 4];
            bl[ni][0] = B32l[i0]; bl[ni][1] = B32l[i0 + 4];
        }
        #pragma unroll
        for (int mi = 0; mi < 2; mi++)
            #pragma unroll
            for (int ni = 0; ni < 4; ni++) {
                mma16816(acc[mi][ni], ah[mi], bh[ni]);
                mma16816(acc[mi][ni], ah[mi], bl[ni]);
                mma16816(acc[mi][ni], al[mi], bh[ni]);
            }
        __syncthreads();
        if (s + 2 < NSTAGE) {
            issue(s + 2, buf);
            asm volatile("cp.async.wait_group 1;");
        } else {
            asm volatile("cp.async.wait_group 0;");
        }
        __syncthreads();
    }

    // epilogue
    #pragma unroll
    for (int mi = 0; mi < 2; mi++) {
        int mrow = bm + wm * 32 + mi * 16 + (lane >> 2);
        #pragma unroll
        for (int ni = 0; ni < 4; ni++) {
            int ncol = bn + wn * 32 + ni * 8 + 2 * (lane & 3);
            #pragma unroll
            for (int rr = 0; rr < 2; rr++) {
                int m = mrow + rr * 8;
                if (m >= M) continue;
                #pragma unroll
                for (int cc = 0; cc < 2; cc++) {
                    int n = ncol + cc;
                    if (n >= 300) continue;
                    float v = acc[mi][ni][rr * 2 + cc] + __ldg(&bias[n]);
                    if (act == 1) v = fmaxf(v, 0.f);
                    else if (act == 2) v = tanhf(v);
                    C[(size_t)m * 300 + n] = v;
                }
            }
        }
    }
}

// ---------------- gate: 5->3->1 MLP over stacked range features ----------------
__global__ void gate_kernel(const float* __restrict__ mr1W, const float* __restrict__ mr1b,
                            const float* __restrict__ mr2W, const float* __restrict__ mr2b) {
    int i = blockIdx.x * blockDim.x + threadIdx.x;
    if (i >= 32000 * 300) return;
    int bt = i / 300;
    int d = i - bt * 300;
    int b = bt / 2000;
    int t = bt - b * 2000;
    float y[5];
    y[0] = g_h[(b * 2000 + t) * 300 + d];
    y[1] = g_h[(32000 + b * 1000 + (t >> 1)) * 300 + d] * 0.5f;
    y[2] = g_h[(48000 + b * 500 + (t >> 2)) * 300 + d] * 0.25f;
    y[3] = g_h[(56064 + b * 200 + t / 10) * 300 + d] * 0.1f;
    y[4] = g_h[(59392 + b * 80 + t / 25) * 300 + d] * 0.04f;
    float acc2 = __ldg(mr2b);
    #pragma unroll
    for (int k = 0; k < 3; k++) {
        float hk = __ldg(&mr1b[k]);
        #pragma unroll
        for (int r = 0; r < 5; r++) hk += __ldg(&mr1W[k * 5 + r]) * y[r];
        hk = fmaxf(hk, 0.f);
        acc2 += __ldg(&mr2W[k]) * hk;
    }
    g_gate[i] = fmaxf(acc2, 0.f);
}

// ---------------- chunked linear scan ----------------
__global__ void scanA_kernel() {
    int ch = blockIdx.x, b = blockIdx.y, d = threadIdx.x;
    int base = (b * 2000 + ch * 50) * 300 + d;
    float a = 1.f, bb = 0.f;
    for (int j = 0; j < 50; j++) {
        float g = g_gate[base + j * 300];
        float z = g_z[base + j * 300];
        a *= g;
        bb = g * (bb - z) + z;
    }
    int o = (b * 40 + ch) * 300 + d;
    g_scA[o] = a;
    g_scB[o] = bb;
}
__global__ void scanB_kernel() {
    int b = blockIdx.x, d = threadIdx.x;
    float c = 0.f;
    for (int ch = 0; ch < 40; ch++) {
        int o = (b * 40 + ch) * 300 + d;
        g_scC[o] = c;
        c = g_scA[o] * c + g_scB[o];
    }
}
__global__ void scanC_kernel() {
    int ch = blockIdx.x, b = blockIdx.y, d = threadIdx.x;
    float c = g_scC[(b * 40 + ch) * 300 + d];
    int base = (b * 2000 + ch * 50) * 300 + d;
    for (int j = 0; j < 50; j++) {
        float g = g_gate[base + j * 300];
        float z = g_z[base + j * 300];
        c = g * (c - z) + z;
        g_enc[base + j * 300] = g_o[base + j * 300] * c;
    }
}

// ---------------- attention 1 ----------------
__global__ void attn1_kernel() {
    __shared__ float sk[30][301];
    __shared__ float srow[8][300];
    __shared__ float sp[8][30];
    int b = blockIdx.y;
    int tid = threadIdx.x;
    for (int i = tid; i < 30 * 300; i += 256) {
        int w = i / 300, k = i - w * 300;
        sk[w][k] = g_k1[(b * 30 + w) * 300 + k];
    }
    __syncthreads();
    int warp = tid >> 5, lane = tid & 31;
    int t = blockIdx.x * 8 + warp;
    const float* row = g_enc + (b * 2000 + t) * 300;
    for (int dd = lane; dd < 300; dd += 32) srow[warp][dd] = row[dd];
    __syncwarp();
    float s = -1e30f;
    if (lane < 30) {
        float a = 0.f;
        for (int k = 0; k < 300; k++) a += srow[warp][k] * sk[lane][k];
        s = a;
    }
    float mx = s;
    #pragma unroll
    for (int o = 16; o; o >>= 1) mx = fmaxf(mx, __shfl_xor_sync(0xffffffffu, mx, o));
    float e = (lane < 30) ? expf(s - mx) : 0.f;
    float sum = e;
    #pragma unroll
    for (int o = 16; o; o >>= 1) sum += __shfl_xor_sync(0xffffffffu, sum, o);
    if (lane < 30) sp[warp][lane] = e / sum;
    __syncwarp();
    const float* qb = g_qf + b * 30 * 300;
    float* outr = g_aoq + (b * 2000 + t) * 300;
    for (int dd = lane; dd < 300; dd += 32) {
        float a = 0.f;
        #pragma unroll 5
        for (int w = 0; w < 30; w++) a += sp[warp][w] * qb[w * 300 + dd];
        outr[dd] = a;
    }
}

// ---------------- attention 2 column-sums ----------------
__global__ void attn2_kernel() {
    __shared__ float sk2[16][301];
    __shared__ float sk3[16][301];
    __shared__ float srow[8][300];
    int ch = blockIdx.x, b = blockIdx.y, opt = blockIdx.z;
    int tid = threadIdx.x, warp = tid >> 5, lane = tid & 31;
    int ob = opt * 16 + b;
    for (int i = tid; i < 16 * 300; i += 256) {
        int w = i / 300, k = i - w * 300;
        sk2[w][k] = g_k2[(ob * 16 + w) * 300 + k];
        sk3[w][k] = g_k3[(ob * 16 + w) * 300 + k];
    }
    __syncthreads();
    const float* kp = (lane < 16) ? &sk2[lane][0] : &sk3[lane - 16][0];
    float acc = 0.f;
    for (int t = ch * 250 + warp; t < ch * 250 + 250; t += 8) {
        const float* row = g_aoq + (b * 2000 + t) * 300;
        for (int dd = lane; dd < 300; dd += 32) srow[warp][dd] = row[dd];
        __syncwarp();
        float s = 0.f;
        for (int k = 0; k < 300; k++) s += srow[warp][k] * kp[k];
        float mx = s;
        #pragma unroll
        for (int o = 8; o; o >>= 1) mx = fmaxf(mx, __shfl_xor_sync(0xffffffffu, mx, o));
        float e = expf(s - mx);
        float sum = e;
        #pragma unroll
        for (int o = 8; o; o >>= 1) sum += __shfl_xor_sync(0xffffffffu, sum, o);
        acc += e / sum;
        __syncwarp();
    }
    atomicAdd(&g_cm[(ob * 2 + (lane >> 4)) * 16 + (lane & 15)], acc);
}

__global__ void zero_cm_kernel() {
    int i = blockIdx.x * blockDim.x + threadIdx.x;
    if (i < 4 * 16 * 2 * 16) g_cm[i] = 0.f;
}

// ---------------- final MLP ----------------
__global__ void final_kernel(const float* __restrict__ as1W, const float* __restrict__ as1b,
                             const float* __restrict__ as2W, const float* __restrict__ as2b,
                             float* __restrict__ out) {
    __shared__ float sav[600];
    __shared__ float sh[75];
    __shared__ float scm[32];
    int bid = blockIdx.x;
    int opt = bid >> 4, b = bid & 15;
    int ob = opt * 16 + b;
    int tid = threadIdx.x;
    if (tid < 32) scm[tid] = g_cm[ob * 32 + tid] * (1.0f / 2000.0f);
    __syncthreads();
    for (int d = tid; d < 300; d += 128) {
        float a2 = 0.f, a3 = 0.f;
        #pragma unroll
        for (int w = 0; w < 16; w++) {
            float ov = g_optf[(ob * 16 + w) * 300 + d];
            a2 += scm[w] * ov;
            a3 += scm[16 + w] * ov;
        }
        sav[d] = a2;
        sav[300 + d] = a3;
    }
    __syncthreads();
    for (int j = tid; j < 75; j += 128) {
        float a = __ldg(&as1b[j]);
        for (int i2 = 0; i2 < 600; i2++) a += __ldg(&as1W[j * 600 + i2]) * sav[i2];
        sh[j] = fmaxf(a, 0.f);
    }
    __syncthreads();
    if (tid == 0) {
        float s = __ldg(as2b);
        for (int j = 0; j < 75; j++) s += __ldg(&as2W[j]) * sh[j];
        out[b * 4 + opt] = s;
    }
}

// ---------------- launch ----------------
extern "C" void kernel_launch(void* const* d_in, const int* in_sizes, int n_in,
                              void* d_out, int out_size) {
    const int* opt_idx[4] = {(const int*)d_in[0], (const int*)d_in[1],
                             (const int*)d_in[2], (const int*)d_in[3]};
    const int* q_idx = (const int*)d_in[4];
    const int* a_idx = (const int*)d_in[5];
    const float* emb = (const float*)d_in[6];
    const float* ceW = (const float*)d_in[7];
    const float* ceb = (const float*)d_in[8];
    const float* mr1W = (const float*)d_in[9];
    const float* mr1b = (const float*)d_in[10];
    const float* mr2W = (const float*)d_in[11];
    const float* mr2b = (const float*)d_in[12];
    const float* Wz = (const float*)d_in[13];
    const float* bz = (const float*)d_in[14];
    const float* Wo = (const float*)d_in[15];
    const float* bo = (const float*)d_in[16];
    const float* f1W = (const float*)d_in[17];
    const float* f1b = (const float*)d_in[18];
    const float* f2W = (const float*)d_in[19];
    const float* f2b = (const float*)d_in[20];
    const float* f3W = (const float*)d_in[21];
    const float* f3b = (const float*)d_in[22];
    const float* as1W = (const float*)d_in[23];
    const float* as1b = (const float*)d_in[24];
    const float* as2W = (const float*)d_in[25];
    const float* as2b = (const float*)d_in[26];

    // weight splits (bf16 hi/lo)
    split_w<<<(450000 + 255) / 256, 256>>>(ceW, 0, 450000);
    split_w<<<(90000 + 255) / 256, 256>>>(Wz, 5, 90000);
    split_w<<<(90000 + 255) / 256, 256>>>(Wo, 6, 90000);
    split_w<<<(90000 + 255) / 256, 256>>>(f1W, 7, 90000);
    split_w<<<(90000 + 255) / 256, 256>>>(f2W, 8, 90000);
    split_w<<<(90000 + 255) / 256, 256>>>(f3W, 9, 90000);

    // embeddings (+ splits)
    gather_split<<<(32000 * 300 + 255) / 256, 256>>>(a_idx, emb, 0, 0, 32000);
    gather_split<<<(480 * 300 + 255) / 256, 256>>>(q_idx, emb, 1, 0, 480);
    for (int o = 0; o < 4; o++)
        gather_split<<<(256 * 300 + 255) / 256, 256>>>(opt_idx[o], emb, 2, o * 256, 256);

    // ContractExpand group sums + GEMM (relu, per-range weights)
    xs_kernel<<<(60672 * 300 + 255) / 256, 256>>>();
    gemm_mma<<<dim3(5, 474), 256>>>(0, 0, ceb, 0, 60672, 1, 1);
    gate_kernel<<<(32000 * 300 + 255) / 256, 256>>>(mr1W, mr1b, mr2W, mr2b);

    // z, o projections (tanh)
    gemm_mma<<<dim3(5, 250), 256>>>(1, 5, bz, 1, 32000, 2, 0);
    gemm_mma<<<dim3(5, 250), 256>>>(1, 6, bo, 2, 32000, 2, 0);

    // chunked scan -> enc
    scanA_kernel<<<dim3(40, 16), 300>>>();
    scanB_kernel<<<16, 300>>>();
    scanC_kernel<<<dim3(40, 16), 300>>>();

    // attention 1
    gemm_mma<<<dim3(5, 4), 256>>>(2, 7, f1b, 3, 480, 0, 0);
    attn1_kernel<<<dim3(250, 16), 256>>>();

    // option keys + attention 2 column sums
    gemm_mma<<<dim3(5, 8), 256>>>(3, 8, f2b, 4, 1024, 0, 0);
    gemm_mma<<<dim3(5, 8), 256>>>(3, 9, f3b, 5, 1024, 0, 0);
    zero_cm_kernel<<<8, 256>>>();
    attn2_kernel<<<dim3(8, 16, 4), 256>>>();

    // final MLP
    final_kernel<<<64, 128>>>(as1W, as1b, as2W, as2b, (float*)d_out);
}